// round 6
// baseline (speedup 1.0000x reference)
#include <cuda_runtime.h>

#define MAXN 100000
#define MAXE 1600000
#define HD   256
#define INF_ 128

// ---------------- scratch ----------------------------------------------------
__device__ float g_ft[(size_t)MAXN * HD];     // 102.4 MB
__device__ float g_el[MAXN * 8];
__device__ float g_er[MAXN * 8];
__device__ int   g_deg[MAXN];
__device__ int   g_rowoff[MAXN + 1];
__device__ int   g_cursor[MAXN];
__device__ int   g_eids[MAXE];
__device__ int   g_bsum[1024];

// ---------------- init --------------------------------------------------------
__global__ void k_init(int n) {
    int i = blockIdx.x * blockDim.x + threadIdx.x;
    if (i < n) g_deg[i] = 0;
}

// ---------------- GEMM + fused el/er epilogue ---------------------------------
__global__ __launch_bounds__(512, 1)
void k_gemm(const float* __restrict__ feat, const float* __restrict__ W,
            const float* __restrict__ al, const float* __restrict__ ar, int n) {
    extern __shared__ float sm[];
    float* Ws = sm;                 // 128 x 256 floats (128 KB)
    float* fs = sm + 32768;         // 128 x 129 padded (66 KB)
    const int tid = threadIdx.x;
    const int n0  = blockIdx.x * 128;

    for (int i = tid; i < 8192; i += 512)
        ((float4*)Ws)[i] = ((const float4*)W)[i];
    for (int i = tid; i < 4096; i += 512) {
        int r = i >> 5, c4 = i & 31;
        float4 v = make_float4(0.f, 0.f, 0.f, 0.f);
        if (n0 + r < n) v = ((const float4*)feat)[(size_t)(n0 + r) * 32 + c4];
        float* d = fs + r * 129 + c4 * 4;
        d[0] = v.x; d[1] = v.y; d[2] = v.z; d[3] = v.w;
    }
    __syncthreads();

    const int cg = tid & 15;        // 16-col group (within head cg>>1)
    const int ng = tid >> 4;        // 4-node group
    unsigned long long acc[32];
#pragma unroll
    for (int i = 0; i < 32; i++) acc[i] = 0ULL;

    const float* f0 = fs + ng * 4 * 129;
    const float* wc = Ws + cg * 16;

#pragma unroll 2
    for (int k = 0; k < 128; k++) {
        unsigned long long a[4];
#pragma unroll
        for (int i = 0; i < 4; i++) {
            unsigned int fb = __float_as_uint(f0[i * 129 + k]);
            asm("mov.b64 %0, {%1, %1};" : "=l"(a[i]) : "r"(fb));
        }
        const ulonglong2* wp = reinterpret_cast<const ulonglong2*>(wc + (size_t)k * HD);
        ulonglong2 w0 = wp[0], w1 = wp[1], w2 = wp[2], w3 = wp[3];
        unsigned long long w[8] = {w0.x, w0.y, w1.x, w1.y, w2.x, w2.y, w3.x, w3.y};
#pragma unroll
        for (int i = 0; i < 4; i++)
#pragma unroll
            for (int j = 0; j < 8; j++)
                asm("fma.rn.f32x2 %0, %1, %2, %0;" : "+l"(acc[i * 8 + j]) : "l"(a[i]), "l"(w[j]));
    }

    float alv[16], arv[16];
#pragma unroll
    for (int j = 0; j < 16; j++) {
        alv[j] = __ldg(al + cg * 16 + j);
        arv[j] = __ldg(ar + cg * 16 + j);
    }

#pragma unroll
    for (int i = 0; i < 4; i++) {
        int node = n0 + ng * 4 + i;
        float pl = 0.f, pr = 0.f;
        float vals[16];
#pragma unroll
        for (int j = 0; j < 8; j++) {
            unsigned int lo, hi;
            asm("mov.b64 {%0, %1}, %2;" : "=r"(lo), "=r"(hi) : "l"(acc[i * 8 + j]));
            float flo = __uint_as_float(lo), fhi = __uint_as_float(hi);
            vals[2 * j] = flo; vals[2 * j + 1] = fhi;
            pl += flo * alv[2 * j] + fhi * alv[2 * j + 1];
            pr += flo * arv[2 * j] + fhi * arv[2 * j + 1];
        }
        pl += __shfl_xor_sync(0xffffffffu, pl, 1);
        pr += __shfl_xor_sync(0xffffffffu, pr, 1);
        if (node < n) {
            float* o = g_ft + (size_t)node * HD + cg * 16;
#pragma unroll
            for (int j = 0; j < 16; j++) o[j] = vals[j];
            if ((cg & 1) == 0) {
                g_el[node * 8 + (cg >> 1)] = pl;
                g_er[node * 8 + (cg >> 1)] = pr;
            }
        }
    }
}

// ---------------- CSR build ----------------------------------------------------
__global__ void k_hist(const int* __restrict__ dst, int e) {
    int i = blockIdx.x * blockDim.x + threadIdx.x;
    if (i < e) atomicAdd(&g_deg[dst[i]], 1);
}

__global__ void k_scan1(int n) {
    __shared__ int sm[1024];
    int i = blockIdx.x * 1024 + threadIdx.x;
    int v = (i < n) ? g_deg[i] : 0;
    sm[threadIdx.x] = v;
    __syncthreads();
    for (int off = 1; off < 1024; off <<= 1) {
        int t = (threadIdx.x >= off) ? sm[threadIdx.x - off] : 0;
        __syncthreads();
        sm[threadIdx.x] += t;
        __syncthreads();
    }
    if (i < n) g_rowoff[i] = sm[threadIdx.x] - v;
    if (threadIdx.x == 1023) g_bsum[blockIdx.x] = sm[1023];
}

__global__ void k_scan2(int nb) {
    if (threadIdx.x == 0 && blockIdx.x == 0) {
        int s = 0;
        for (int b = 0; b < nb; b++) { int t = g_bsum[b]; g_bsum[b] = s; s += t; }
    }
}

__global__ void k_scan3(int n, int e) {
    int i = blockIdx.x * 1024 + threadIdx.x;
    if (i < n) {
        int r = g_rowoff[i] + g_bsum[i >> 10];
        g_rowoff[i] = r;
        g_cursor[i] = r;
    }
    if (i == 0) g_rowoff[n] = e;
}

__global__ void k_scatter(const int* __restrict__ dst, int e) {
    int i = blockIdx.x * blockDim.x + threadIdx.x;
    if (i < e) {
        int p = atomicAdd(&g_cursor[dst[i]], 1);
        g_eids[p] = i;
    }
}

// ---- fused online-softmax + aggregate (warp/node, MLP-batched gather) --------
__global__ __launch_bounds__(256)
void k_agg(const int* __restrict__ src, const float* __restrict__ bias,
           float* __restrict__ out_h, float* __restrict__ out_attn, int n) {
    const unsigned FULL = 0xffffffffu;
    int warp = (blockIdx.x * blockDim.x + threadIdx.x) >> 5;
    int lane = threadIdx.x & 31;
    if (warp >= n) return;
    const int beg = g_rowoff[warp], end = g_rowoff[warp + 1];

    float4 er0 = *(const float4*)(g_er + (size_t)warp * 8);
    float4 er1 = *(const float4*)(g_er + (size_t)warp * 8 + 4);
    const float er[8] = {er0.x, er0.y, er0.z, er0.w, er1.x, er1.y, er1.z, er1.w};

    float m[8], s_[8], acc[8];
#pragma unroll
    for (int h = 0; h < 8; h++) { m[h] = -1e30f; s_[h] = 0.f; acc[h] = 0.f; }

    for (int base = beg; base < end; base += 32) {
        const int p = base + lane;
        const bool valid = p < end;
        int e = 0, sr = 0;
        if (valid) { e = g_eids[p]; sr = src[e]; }

        // lane-parallel logits (each lane owns one edge of this batch)
        float v[8];
        if (valid) {
            float4 l0 = *(const float4*)(g_el + (size_t)sr * 8);
            float4 l1 = *(const float4*)(g_el + (size_t)sr * 8 + 4);
            float lv[8] = {l0.x, l0.y, l0.z, l0.w, l1.x, l1.y, l1.z, l1.w};
#pragma unroll
            for (int h = 0; h < 8; h++) {
                float t = lv[h] + er[h];
                v[h] = t > 0.f ? t : 0.2f * t;
            }
        } else {
#pragma unroll
            for (int h = 0; h < 8; h++) v[h] = -1e30f;
        }

        // batch max (warp-uniform), online rescale
        float bm[8];
#pragma unroll
        for (int h = 0; h < 8; h++) bm[h] = v[h];
#pragma unroll
        for (int off = 16; off; off >>= 1)
#pragma unroll
            for (int h = 0; h < 8; h++)
                bm[h] = fmaxf(bm[h], __shfl_xor_sync(FULL, bm[h], off));
#pragma unroll
        for (int h = 0; h < 8; h++) {
            float nm = fmaxf(m[h], bm[h]);
            float sc = __expf(m[h] - nm);
            s_[h] *= sc; acc[h] *= sc; m[h] = nm;
        }

        // lane-parallel weights + partial sums
        float w[8];
#pragma unroll
        for (int h = 0; h < 8; h++) {
            w[h] = valid ? __expf(v[h] - m[h]) : 0.f;
            s_[h] += w[h];
        }

        // gather + accumulate, 4 edges in flight (32 independent LDGs)
        const int cnt = min(32, end - base);
        int j = 0;
        for (; j + 4 <= cnt; j += 4) {
            float f[4][8];
#pragma unroll
            for (int q = 0; q < 4; q++) {
                int sj = __shfl_sync(FULL, sr, j + q);
                const float* fp = g_ft + (size_t)sj * HD + lane;
#pragma unroll
                for (int h = 0; h < 8; h++) f[q][h] = fp[h * 32];
            }
#pragma unroll
            for (int q = 0; q < 4; q++)
#pragma unroll
                for (int h = 0; h < 8; h++) {
                    float a = __shfl_sync(FULL, w[h], j + q);
                    acc[h] += a * f[q][h];
                }
        }
        for (; j < cnt; j++) {
            int sj = __shfl_sync(FULL, sr, j);
            const float* fp = g_ft + (size_t)sj * HD + lane;
            float f[8];
#pragma unroll
            for (int h = 0; h < 8; h++) f[h] = fp[h * 32];
#pragma unroll
            for (int h = 0; h < 8; h++) {
                float a = __shfl_sync(FULL, w[h], j);
                acc[h] += a * f[h];
            }
        }
    }

    // reduce sums across lanes
#pragma unroll
    for (int off = 16; off; off >>= 1)
#pragma unroll
        for (int h = 0; h < 8; h++)
            s_[h] += __shfl_xor_sync(FULL, s_[h], off);
    float inv[8];
#pragma unroll
    for (int h = 0; h < 8; h++) inv[h] = (s_[h] > 0.f) ? 1.f / s_[h] : 0.f;

    // attn output: recompute lane-parallel from L2-resident g_el (no readback)
    for (int p = beg + lane; p < end; p += 32) {
        int e = g_eids[p];
        int s = src[e];
        float4 l0 = *(const float4*)(g_el + (size_t)s * 8);
        float4 l1 = *(const float4*)(g_el + (size_t)s * 8 + 4);
        float lv[8] = {l0.x, l0.y, l0.z, l0.w, l1.x, l1.y, l1.z, l1.w};
        float a[8];
#pragma unroll
        for (int h = 0; h < 8; h++) {
            float t = lv[h] + er[h];
            t = t > 0.f ? t : 0.2f * t;
            a[h] = __expf(t - m[h]) * inv[h];
        }
        *(float4*)(out_attn + (size_t)e * 8)     = make_float4(a[0], a[1], a[2], a[3]);
        *(float4*)(out_attn + (size_t)e * 8 + 4) = make_float4(a[4], a[5], a[6], a[7]);
    }

    float msum = 0.f;
#pragma unroll
    for (int h = 0; h < 8; h++)
        msum += acc[h] * inv[h] + bias[h * 32 + lane];
    out_h[(size_t)warp * 32 + lane] = msum * 0.125f;
}

// ---------------- launch --------------------------------------------------------
extern "C" void kernel_launch(void* const* d_in, const int* in_sizes, int n_in,
                              void* d_out, int out_size) {
    const float* feat = (const float*)d_in[0];
    const int*   src  = (const int*)d_in[1];
    const int*   dst  = (const int*)d_in[2];
    const float* W    = (const float*)d_in[3];
    const float* al   = (const float*)d_in[4];
    const float* ar   = (const float*)d_in[5];
    const float* bias = (const float*)d_in[6];

    int n = in_sizes[0] / INF_;
    int e = in_sizes[1];

    float* out      = (float*)d_out;
    float* out_h    = out;                   // [n, 32]
    float* out_attn = out + (size_t)n * 32;  // [e, 8]

    const int SMEM = (32768 + 128 * 129) * 4;
    cudaFuncSetAttribute(k_gemm, cudaFuncAttributeMaxDynamicSharedMemorySize, SMEM);

    int nb = (n + 1023) / 1024;

    // Order chosen so the profiled launch (index 3) is k_gemm.
    k_init<<<(n + 255) / 256, 256>>>(n);                 // 0
    k_hist<<<(e + 255) / 256, 256>>>(dst, e);            // 1
    k_scan1<<<nb, 1024>>>(n);                            // 2
    k_gemm<<<(n + 127) / 128, 512, SMEM>>>(feat, W, al, ar, n);  // 3  <-- profiled
    k_scan2<<<1, 32>>>(nb);                              // 4
    k_scan3<<<nb, 1024>>>(n, e);                         // 5
    k_scatter<<<(e + 255) / 256, 256>>>(dst, e);         // 6
    k_agg<<<(n + 7) / 8, 256>>>(src, bias, out_h, out_attn, n);  // 7
}

// round 7
// speedup vs baseline: 2.0990x; 2.0990x over previous
#include <cuda_runtime.h>

#define MAXN 100000
#define MAXE 1600000
#define HD   256
#define INF_ 128

// ---------------- scratch ----------------------------------------------------
__device__ float g_ft[(size_t)MAXN * HD];     // 102.4 MB
__device__ float g_el[MAXN * 8];
__device__ float g_er[MAXN * 8];
__device__ float g_bmean[32];
__device__ int   g_deg[MAXN];
__device__ int   g_rowoff[MAXN + 1];
__device__ int   g_cursor[MAXN];
__device__ int   g_eids[MAXE];
__device__ int   g_bsum[1024];

// ---------------- init --------------------------------------------------------
__global__ void k_init(int n) {
    int i = blockIdx.x * blockDim.x + threadIdx.x;
    if (i < n) g_deg[i] = 0;
}

__global__ void k_bias(const float* __restrict__ bias) {
    int c = threadIdx.x;           // 0..31
    float s = 0.f;
#pragma unroll
    for (int h = 0; h < 8; h++) s += bias[h * 32 + c];
    g_bmean[c] = s * 0.125f;
}

// ---------------- GEMM + fused el/er epilogue ---------------------------------
// block 512 = 16 warps. warp w -> cols [w*16, w*16+16); lane l -> nodes 4l..4l+3
// Ws reads: warp-uniform broadcast (conflict-free). fs: transposed [k][node],
// LDS.128 covers 512 contiguous bytes per warp (conflict-free).
__global__ __launch_bounds__(512, 1)
void k_gemm(const float* __restrict__ feat, const float* __restrict__ W,
            const float* __restrict__ al, const float* __restrict__ ar, int n) {
    extern __shared__ float sm[];
    float* Ws  = sm;                         // 128 x 256          (128 KB)
    float* fs  = sm + 32768;                 // 128 k x 132 nodes  (67.6 KB)
    float* pel = sm + 32768 + 128 * 132;     // 128 x 17 partial el (8.5 KB)
    float* per = pel + 128 * 17;             // 128 x 17 partial er
    const int tid = threadIdx.x;
    const int n0  = blockIdx.x * 128;

    for (int i = tid; i < 8192; i += 512)
        ((float4*)Ws)[i] = ((const float4*)W)[i];
    // transpose feat tile into fs[k][node] (row stride 132 floats)
    for (int i = tid; i < 4096; i += 512) {
        int r = i >> 5, c4 = i & 31;         // node r, k-group c4
        float4 v = make_float4(0.f, 0.f, 0.f, 0.f);
        if (n0 + r < n) v = ((const float4*)feat)[(size_t)(n0 + r) * 32 + c4];
        fs[(4 * c4 + 0) * 132 + r] = v.x;
        fs[(4 * c4 + 1) * 132 + r] = v.y;
        fs[(4 * c4 + 2) * 132 + r] = v.z;
        fs[(4 * c4 + 3) * 132 + r] = v.w;
    }
    __syncthreads();

    const int w    = tid >> 5;   // warp = col group
    const int lane = tid & 31;

    unsigned long long acc[32];  // [node i][col pair j]
#pragma unroll
    for (int i = 0; i < 32; i++) acc[i] = 0ULL;

    const float* fp = fs + 4 * lane;
    const float* wp = Ws + w * 16;

#pragma unroll 2
    for (int k = 0; k < 128; k++) {
        float4 f = *(const float4*)(fp + k * 132);            // nodes 4l..4l+3
        const ulonglong2* wv = (const ulonglong2*)(wp + (size_t)k * HD);
        ulonglong2 u0 = wv[0], u1 = wv[1], u2 = wv[2], u3 = wv[3];  // broadcast
        unsigned long long wr[8] = {u0.x, u0.y, u1.x, u1.y, u2.x, u2.y, u3.x, u3.y};
        unsigned long long a[4];
        asm("mov.b64 %0, {%1, %1};" : "=l"(a[0]) : "r"(__float_as_uint(f.x)));
        asm("mov.b64 %0, {%1, %1};" : "=l"(a[1]) : "r"(__float_as_uint(f.y)));
        asm("mov.b64 %0, {%1, %1};" : "=l"(a[2]) : "r"(__float_as_uint(f.z)));
        asm("mov.b64 %0, {%1, %1};" : "=l"(a[3]) : "r"(__float_as_uint(f.w)));
#pragma unroll
        for (int i = 0; i < 4; i++)
#pragma unroll
            for (int j = 0; j < 8; j++)
                asm("fma.rn.f32x2 %0, %1, %2, %0;" : "+l"(acc[i * 8 + j]) : "l"(a[i]), "l"(wr[j]));
    }

    float alv[16], arv[16];
#pragma unroll
    for (int j = 0; j < 16; j++) {
        alv[j] = __ldg(al + w * 16 + j);
        arv[j] = __ldg(ar + w * 16 + j);
    }

#pragma unroll
    for (int i = 0; i < 4; i++) {
        int node = 4 * lane + i;             // tile-local
        float pl = 0.f, pr = 0.f;
        float vals[16];
#pragma unroll
        for (int j = 0; j < 8; j++) {
            unsigned int lo, hi;
            asm("mov.b64 {%0, %1}, %2;" : "=r"(lo), "=r"(hi) : "l"(acc[i * 8 + j]));
            float flo = __uint_as_float(lo), fhi = __uint_as_float(hi);
            vals[2 * j] = flo; vals[2 * j + 1] = fhi;
            pl += flo * alv[2 * j] + fhi * alv[2 * j + 1];
            pr += flo * arv[2 * j] + fhi * arv[2 * j + 1];
        }
        pel[node * 17 + w] = pl;
        per[node * 17 + w] = pr;
        if (n0 + node < n) {
            float4* o = (float4*)(g_ft + (size_t)(n0 + node) * HD + w * 16);
            o[0] = make_float4(vals[0],  vals[1],  vals[2],  vals[3]);
            o[1] = make_float4(vals[4],  vals[5],  vals[6],  vals[7]);
            o[2] = make_float4(vals[8],  vals[9],  vals[10], vals[11]);
            o[3] = make_float4(vals[12], vals[13], vals[14], vals[15]);
        }
    }
    __syncthreads();

    // final el/er: sum the two 16-col halves of each head
    for (int idx = tid; idx < 1024; idx += 512) {
        int node = idx >> 3, h = idx & 7;
        if (n0 + node < n) {
            g_el[(n0 + node) * 8 + h] = pel[node * 17 + 2 * h] + pel[node * 17 + 2 * h + 1];
            g_er[(n0 + node) * 8 + h] = per[node * 17 + 2 * h] + per[node * 17 + 2 * h + 1];
        }
    }
}

// ---------------- CSR build ----------------------------------------------------
__global__ void k_hist(const int* __restrict__ dst, int e) {
    int i = blockIdx.x * blockDim.x + threadIdx.x;
    if (i < e) atomicAdd(&g_deg[dst[i]], 1);
}

__global__ void k_scan1(int n) {
    __shared__ int sm[1024];
    int i = blockIdx.x * 1024 + threadIdx.x;
    int v = (i < n) ? g_deg[i] : 0;
    sm[threadIdx.x] = v;
    __syncthreads();
    for (int off = 1; off < 1024; off <<= 1) {
        int t = (threadIdx.x >= off) ? sm[threadIdx.x - off] : 0;
        __syncthreads();
        sm[threadIdx.x] += t;
        __syncthreads();
    }
    if (i < n) g_rowoff[i] = sm[threadIdx.x] - v;
    if (threadIdx.x == 1023) g_bsum[blockIdx.x] = sm[1023];
}

__global__ void k_scan2(int nb) {
    if (threadIdx.x == 0 && blockIdx.x == 0) {
        int s = 0;
        for (int b = 0; b < nb; b++) { int t = g_bsum[b]; g_bsum[b] = s; s += t; }
    }
}

__global__ void k_scan3(int n, int e) {
    int i = blockIdx.x * 1024 + threadIdx.x;
    if (i < n) {
        int r = g_rowoff[i] + g_bsum[i >> 10];
        g_rowoff[i] = r;
        g_cursor[i] = r;
    }
    if (i == 0) g_rowoff[n] = e;
}

__global__ void k_scatter(const int* __restrict__ dst, int e) {
    int i = blockIdx.x * blockDim.x + threadIdx.x;
    if (i < e) {
        int p = atomicAdd(&g_cursor[dst[i]], 1);
        g_eids[p] = i;
    }
}

__device__ __forceinline__ float pick4(float a0, float a1, float a2, float a3, int i) {
    float x = (i & 1) ? a1 : a0;
    float y = (i & 1) ? a3 : a2;
    return (i & 2) ? y : x;
}

// ---- fused online-softmax + aggregate: warp/node, vectorized gather ----------
// lane l owns cols 4l..4l+3 (head l>>3) and 128+4l..+3 (head 4+(l>>3)).
__global__ __launch_bounds__(256)
void k_agg(const int* __restrict__ src, float* __restrict__ out_h,
           float* __restrict__ out_attn, int n) {
    __shared__ float s_wlo[8][32][4];
    __shared__ float s_whi[8][32][4];
    const unsigned FULL = 0xffffffffu;
    const int wid  = threadIdx.x >> 5;
    const int lane = threadIdx.x & 31;
    const int node = blockIdx.x * 8 + wid;
    if (node >= n) return;
    const int h0 = lane >> 3;
    const int beg = g_rowoff[node], end = g_rowoff[node + 1];

    float4 er0 = *(const float4*)(g_er + (size_t)node * 8);
    float4 er1 = *(const float4*)(g_er + (size_t)node * 8 + 4);
    const float er[8] = {er0.x, er0.y, er0.z, er0.w, er1.x, er1.y, er1.z, er1.w};

    float m[8], s_[8];
#pragma unroll
    for (int h = 0; h < 8; h++) { m[h] = -1e30f; s_[h] = 0.f; }
    float4 acc0 = make_float4(0.f, 0.f, 0.f, 0.f);
    float4 acc1 = make_float4(0.f, 0.f, 0.f, 0.f);

    for (int base = beg; base < end; base += 32) {
        const int p = base + lane;
        const bool valid = p < end;
        int sr = 0;
        if (valid) sr = src[g_eids[p]];

        float v[8];
        if (valid) {
            float4 l0 = *(const float4*)(g_el + (size_t)sr * 8);
            float4 l1 = *(const float4*)(g_el + (size_t)sr * 8 + 4);
            float lv[8] = {l0.x, l0.y, l0.z, l0.w, l1.x, l1.y, l1.z, l1.w};
#pragma unroll
            for (int h = 0; h < 8; h++) {
                float t = lv[h] + er[h];
                v[h] = t > 0.f ? t : 0.2f * t;
            }
        } else {
#pragma unroll
            for (int h = 0; h < 8; h++) v[h] = -1e30f;
        }

        float bm[8];
#pragma unroll
        for (int h = 0; h < 8; h++) bm[h] = v[h];
#pragma unroll
        for (int off = 16; off; off >>= 1)
#pragma unroll
            for (int h = 0; h < 8; h++)
                bm[h] = fmaxf(bm[h], __shfl_xor_sync(FULL, bm[h], off));

        float sc[8];
#pragma unroll
        for (int h = 0; h < 8; h++) {
            float nm = fmaxf(m[h], bm[h]);
            sc[h] = __expf(m[h] - nm);
            s_[h] *= sc[h];
            m[h] = nm;
        }
        float scA = pick4(sc[0], sc[1], sc[2], sc[3], h0);
        float scB = pick4(sc[4], sc[5], sc[6], sc[7], h0);
        acc0.x *= scA; acc0.y *= scA; acc0.z *= scA; acc0.w *= scA;
        acc1.x *= scB; acc1.y *= scB; acc1.z *= scB; acc1.w *= scB;

        float w[8];
#pragma unroll
        for (int h = 0; h < 8; h++) {
            w[h] = valid ? __expf(v[h] - m[h]) : 0.f;
            s_[h] += w[h];
        }
        *(float4*)&s_wlo[wid][lane][0] = make_float4(w[0], w[1], w[2], w[3]);
        *(float4*)&s_whi[wid][lane][0] = make_float4(w[4], w[5], w[6], w[7]);
        __syncwarp();

        const int cnt = min(32, end - base);
        int j = 0;
        for (; j + 2 <= cnt; j += 2) {
            int s0 = __shfl_sync(FULL, sr, j);
            int s1 = __shfl_sync(FULL, sr, j + 1);
            const float4* q0 = (const float4*)(g_ft + (size_t)s0 * HD);
            const float4* q1 = (const float4*)(g_ft + (size_t)s1 * HD);
            float4 a0 = q0[lane], a1 = q0[32 + lane];
            float4 b0 = q1[lane], b1 = q1[32 + lane];
            float wa0 = s_wlo[wid][j][h0],     wa1 = s_whi[wid][j][h0];
            float wb0 = s_wlo[wid][j + 1][h0], wb1 = s_whi[wid][j + 1][h0];
            acc0.x += wa0 * a0.x; acc0.y += wa0 * a0.y; acc0.z += wa0 * a0.z; acc0.w += wa0 * a0.w;
            acc1.x += wa1 * a1.x; acc1.y += wa1 * a1.y; acc1.z += wa1 * a1.z; acc1.w += wa1 * a1.w;
            acc0.x += wb0 * b0.x; acc0.y += wb0 * b0.y; acc0.z += wb0 * b0.z; acc0.w += wb0 * b0.w;
            acc1.x += wb1 * b1.x; acc1.y += wb1 * b1.y; acc1.z += wb1 * b1.z; acc1.w += wb1 * b1.w;
        }
        if (j < cnt) {
            int s0 = __shfl_sync(FULL, sr, j);
            const float4* q0 = (const float4*)(g_ft + (size_t)s0 * HD);
            float4 a0 = q0[lane], a1 = q0[32 + lane];
            float wa0 = s_wlo[wid][j][h0], wa1 = s_whi[wid][j][h0];
            acc0.x += wa0 * a0.x; acc0.y += wa0 * a0.y; acc0.z += wa0 * a0.z; acc0.w += wa0 * a0.w;
            acc1.x += wa1 * a1.x; acc1.y += wa1 * a1.y; acc1.z += wa1 * a1.z; acc1.w += wa1 * a1.w;
        }
        __syncwarp();
    }

    // lane-sum reduction of s_
#pragma unroll
    for (int off = 16; off; off >>= 1)
#pragma unroll
        for (int h = 0; h < 8; h++)
            s_[h] += __shfl_xor_sync(FULL, s_[h], off);
    float inv[8];
#pragma unroll
    for (int h = 0; h < 8; h++) inv[h] = (s_[h] > 0.f) ? 1.f / s_[h] : 0.f;

    // attn output: recompute lane-parallel
    for (int p = beg + lane; p < end; p += 32) {
        int e = g_eids[p];
        int s = src[e];
        float4 l0 = *(const float4*)(g_el + (size_t)s * 8);
        float4 l1 = *(const float4*)(g_el + (size_t)s * 8 + 4);
        float lv[8] = {l0.x, l0.y, l0.z, l0.w, l1.x, l1.y, l1.z, l1.w};
        float a[8];
#pragma unroll
        for (int h = 0; h < 8; h++) {
            float t = lv[h] + er[h];
            t = t > 0.f ? t : 0.2f * t;
            a[h] = __expf(t - m[h]) * inv[h];
        }
        *(float4*)(out_attn + (size_t)e * 8)     = make_float4(a[0], a[1], a[2], a[3]);
        *(float4*)(out_attn + (size_t)e * 8 + 4) = make_float4(a[4], a[5], a[6], a[7]);
    }

    // h output: normalize, sum over heads across lanes, mean
    float invA = pick4(inv[0], inv[1], inv[2], inv[3], h0);
    float invB = pick4(inv[4], inv[5], inv[6], inv[7], h0);
    float4 y;
    y.x = acc0.x * invA + acc1.x * invB;
    y.y = acc0.y * invA + acc1.y * invB;
    y.z = acc0.z * invA + acc1.z * invB;
    y.w = acc0.w * invA + acc1.w * invB;
#pragma unroll
    for (int off = 8; off <= 16; off <<= 1) {
        y.x += __shfl_xor_sync(FULL, y.x, off);
        y.y += __shfl_xor_sync(FULL, y.y, off);
        y.z += __shfl_xor_sync(FULL, y.z, off);
        y.w += __shfl_xor_sync(FULL, y.w, off);
    }
    if (lane < 8) {
        float4 bm4 = ((const float4*)g_bmean)[lane];
        ((float4*)(out_h + (size_t)node * 32))[lane] =
            make_float4(y.x * 0.125f + bm4.x, y.y * 0.125f + bm4.y,
                        y.z * 0.125f + bm4.z, y.w * 0.125f + bm4.w);
    }
}

// ---------------- launch --------------------------------------------------------
extern "C" void kernel_launch(void* const* d_in, const int* in_sizes, int n_in,
                              void* d_out, int out_size) {
    const float* feat = (const float*)d_in[0];
    const int*   src  = (const int*)d_in[1];
    const int*   dst  = (const int*)d_in[2];
    const float* W    = (const float*)d_in[3];
    const float* al   = (const float*)d_in[4];
    const float* ar   = (const float*)d_in[5];
    const float* bias = (const float*)d_in[6];

    int n = in_sizes[0] / INF_;
    int e = in_sizes[1];

    float* out      = (float*)d_out;
    float* out_h    = out;                   // [n, 32]
    float* out_attn = out + (size_t)n * 32;  // [e, 8]

    const int SMEM = (32768 + 128 * 132 + 2 * 128 * 17) * 4;   // ~216 KB
    cudaFuncSetAttribute(k_gemm, cudaFuncAttributeMaxDynamicSharedMemorySize, SMEM);

    int nb = (n + 1023) / 1024;

    k_init<<<(n + 255) / 256, 256>>>(n);                          // 0
    k_hist<<<(e + 255) / 256, 256>>>(dst, e);                     // 1
    k_scan1<<<nb, 1024>>>(n);                                     // 2
    k_gemm<<<(n + 127) / 128, 512, SMEM>>>(feat, W, al, ar, n);   // 3 <- profiled
    k_scan2<<<1, 32>>>(nb);                                       // 4
    k_scan3<<<nb, 1024>>>(n, e);                                  // 5
    k_scatter<<<(e + 255) / 256, 256>>>(dst, e);                  // 6
    k_bias<<<1, 32>>>(bias);                                      // 7
    k_agg<<<(n + 7) / 8, 256>>>(src, out_h, out_attn, n);         // 8
}

// round 8
// speedup vs baseline: 2.4908x; 1.1867x over previous
#include <cuda_runtime.h>
#include <cuda_fp16.h>

#define MAXN 100000
#define MAXE 1600000
#define HD   256
#define INF_ 128

// ---------------- scratch ----------------------------------------------------
__device__ __half g_fth[(size_t)MAXN * HD];   // 51.2 MB (L2-resident)
__device__ float  g_el[MAXN * 8];
__device__ float  g_er[MAXN * 8];
__device__ float  g_bmean[32];
__device__ int    g_deg[MAXN];
__device__ int    g_rowoff[MAXN + 1];
__device__ int    g_cursor[MAXN];
__device__ int    g_eids[MAXE];
__device__ int    g_bsum[1024];

// ---------------- init --------------------------------------------------------
__global__ void k_init(int n) {
    int i = blockIdx.x * blockDim.x + threadIdx.x;
    if (i < n) g_deg[i] = 0;
}

__global__ void k_bias(const float* __restrict__ bias) {
    int c = threadIdx.x;
    float s = 0.f;
#pragma unroll
    for (int h = 0; h < 8; h++) s += bias[h * 32 + c];
    g_bmean[c] = s * 0.125f;
}

// ---------------- GEMM + fused el/er epilogue, fp16 ft store -------------------
__global__ __launch_bounds__(512, 1)
void k_gemm(const float* __restrict__ feat, const float* __restrict__ W,
            const float* __restrict__ al, const float* __restrict__ ar, int n) {
    extern __shared__ float sm[];
    float* Ws  = sm;                         // 128 x 256
    float* fs  = sm + 32768;                 // 128 k x 132 nodes
    float* pel = sm + 32768 + 128 * 132;
    float* per = pel + 128 * 17;
    const int tid = threadIdx.x;
    const int n0  = blockIdx.x * 128;

    for (int i = tid; i < 8192; i += 512)
        ((float4*)Ws)[i] = ((const float4*)W)[i];
    for (int i = tid; i < 4096; i += 512) {
        int r = i >> 5, c4 = i & 31;
        float4 v = make_float4(0.f, 0.f, 0.f, 0.f);
        if (n0 + r < n) v = ((const float4*)feat)[(size_t)(n0 + r) * 32 + c4];
        fs[(4 * c4 + 0) * 132 + r] = v.x;
        fs[(4 * c4 + 1) * 132 + r] = v.y;
        fs[(4 * c4 + 2) * 132 + r] = v.z;
        fs[(4 * c4 + 3) * 132 + r] = v.w;
    }
    __syncthreads();

    const int w    = tid >> 5;
    const int lane = tid & 31;

    unsigned long long acc[32];
#pragma unroll
    for (int i = 0; i < 32; i++) acc[i] = 0ULL;

    const float* fp = fs + 4 * lane;
    const float* wp = Ws + w * 16;

#pragma unroll 2
    for (int k = 0; k < 128; k++) {
        float4 f = *(const float4*)(fp + k * 132);
        const ulonglong2* wv = (const ulonglong2*)(wp + (size_t)k * HD);
        ulonglong2 u0 = wv[0], u1 = wv[1], u2 = wv[2], u3 = wv[3];
        unsigned long long wr[8] = {u0.x, u0.y, u1.x, u1.y, u2.x, u2.y, u3.x, u3.y};
        unsigned long long a[4];
        asm("mov.b64 %0, {%1, %1};" : "=l"(a[0]) : "r"(__float_as_uint(f.x)));
        asm("mov.b64 %0, {%1, %1};" : "=l"(a[1]) : "r"(__float_as_uint(f.y)));
        asm("mov.b64 %0, {%1, %1};" : "=l"(a[2]) : "r"(__float_as_uint(f.z)));
        asm("mov.b64 %0, {%1, %1};" : "=l"(a[3]) : "r"(__float_as_uint(f.w)));
#pragma unroll
        for (int i = 0; i < 4; i++)
#pragma unroll
            for (int j = 0; j < 8; j++)
                asm("fma.rn.f32x2 %0, %1, %2, %0;" : "+l"(acc[i * 8 + j]) : "l"(a[i]), "l"(wr[j]));
    }

    float alv[16], arv[16];
#pragma unroll
    for (int j = 0; j < 16; j++) {
        alv[j] = __ldg(al + w * 16 + j);
        arv[j] = __ldg(ar + w * 16 + j);
    }

#pragma unroll
    for (int i = 0; i < 4; i++) {
        int node = 4 * lane + i;
        float pl = 0.f, pr = 0.f;
        __half2 hv[8];
#pragma unroll
        for (int j = 0; j < 8; j++) {
            unsigned int lo, hi;
            asm("mov.b64 {%0, %1}, %2;" : "=r"(lo), "=r"(hi) : "l"(acc[i * 8 + j]));
            float flo = __uint_as_float(lo), fhi = __uint_as_float(hi);
            hv[j] = __floats2half2_rn(flo, fhi);
            pl += flo * alv[2 * j] + fhi * alv[2 * j + 1];
            pr += flo * arv[2 * j] + fhi * arv[2 * j + 1];
        }
        pel[node * 17 + w] = pl;
        per[node * 17 + w] = pr;
        if (n0 + node < n) {
            uint4* o = (uint4*)(g_fth + (size_t)(n0 + node) * HD + w * 16);
            o[0] = *(uint4*)&hv[0];
            o[1] = *(uint4*)&hv[4];
        }
    }
    __syncthreads();

    for (int idx = tid; idx < 1024; idx += 512) {
        int node = idx >> 3, h = idx & 7;
        if (n0 + node < n) {
            g_el[(n0 + node) * 8 + h] = pel[node * 17 + 2 * h] + pel[node * 17 + 2 * h + 1];
            g_er[(n0 + node) * 8 + h] = per[node * 17 + 2 * h] + per[node * 17 + 2 * h + 1];
        }
    }
}

// ---------------- CSR build ----------------------------------------------------
__global__ void k_hist(const int* __restrict__ dst, int e) {
    int i = blockIdx.x * blockDim.x + threadIdx.x;
    if (i < e) atomicAdd(&g_deg[dst[i]], 1);
}

__global__ void k_scan1(int n) {
    __shared__ int sm[1024];
    int i = blockIdx.x * 1024 + threadIdx.x;
    int v = (i < n) ? g_deg[i] : 0;
    sm[threadIdx.x] = v;
    __syncthreads();
    for (int off = 1; off < 1024; off <<= 1) {
        int t = (threadIdx.x >= off) ? sm[threadIdx.x - off] : 0;
        __syncthreads();
        sm[threadIdx.x] += t;
        __syncthreads();
    }
    if (i < n) g_rowoff[i] = sm[threadIdx.x] - v;
    if (threadIdx.x == 1023) g_bsum[blockIdx.x] = sm[1023];
}

__global__ void k_scan2(int nb) {
    if (threadIdx.x == 0 && blockIdx.x == 0) {
        int s = 0;
        for (int b = 0; b < nb; b++) { int t = g_bsum[b]; g_bsum[b] = s; s += t; }
    }
}

__global__ void k_scan3(int n, int e) {
    int i = blockIdx.x * 1024 + threadIdx.x;
    if (i < n) {
        int r = g_rowoff[i] + g_bsum[i >> 10];
        g_rowoff[i] = r;
        g_cursor[i] = r;
    }
    if (i == 0) g_rowoff[n] = e;
}

__global__ void k_scatter(const int* __restrict__ dst, int e) {
    int i = blockIdx.x * blockDim.x + threadIdx.x;
    if (i < e) {
        int p = atomicAdd(&g_cursor[dst[i]], 1);
        g_eids[p] = i;
    }
}

__device__ __forceinline__ float pick4(float a0, float a1, float a2, float a3, int i) {
    float x = (i & 1) ? a1 : a0;
    float y = (i & 1) ? a3 : a2;
    return (i & 2) ? y : x;
}
__device__ __forceinline__ float pick8(const float v0, const float v1, const float v2,
                                       const float v3, const float v4, const float v5,
                                       const float v6, const float v7, int i) {
    float a = pick4(v0, v1, v2, v3, i & 3);
    float b = pick4(v4, v5, v6, v7, i & 3);
    return (i & 4) ? b : a;
}

// ---- fused online-softmax + aggregate: warp/node, fp16 gather ----------------
// lane l owns cols 8l..8l+7 (all in head h0 = l>>2) -> ONE weight per edge/lane.
__global__ __launch_bounds__(256)
void k_agg(const int* __restrict__ src, float* __restrict__ out_h,
           float* __restrict__ out_attn, int n) {
    __shared__ float s_w[8][32][8];
    const unsigned FULL = 0xffffffffu;
    const int wid  = threadIdx.x >> 5;
    const int lane = threadIdx.x & 31;
    const int node = blockIdx.x * 8 + wid;
    if (node >= n) return;
    const int h0 = lane >> 2;
    const int beg = g_rowoff[node], end = g_rowoff[node + 1];

    float4 er0 = *(const float4*)(g_er + (size_t)node * 8);
    float4 er1 = *(const float4*)(g_er + (size_t)node * 8 + 4);
    const float er[8] = {er0.x, er0.y, er0.z, er0.w, er1.x, er1.y, er1.z, er1.w};

    float m[8], s_[8], acc[8];
#pragma unroll
    for (int h = 0; h < 8; h++) { m[h] = -1e30f; s_[h] = 0.f; acc[h] = 0.f; }

    for (int base = beg; base < end; base += 32) {
        const int p = base + lane;
        const bool valid = p < end;
        int sr = 0;
        if (valid) sr = src[g_eids[p]];

        float v[8];
        if (valid) {
            float4 l0 = *(const float4*)(g_el + (size_t)sr * 8);
            float4 l1 = *(const float4*)(g_el + (size_t)sr * 8 + 4);
            float lv[8] = {l0.x, l0.y, l0.z, l0.w, l1.x, l1.y, l1.z, l1.w};
#pragma unroll
            for (int h = 0; h < 8; h++) {
                float t = lv[h] + er[h];
                v[h] = t > 0.f ? t : 0.2f * t;
            }
        } else {
#pragma unroll
            for (int h = 0; h < 8; h++) v[h] = -1e30f;
        }

        float bm[8];
#pragma unroll
        for (int h = 0; h < 8; h++) bm[h] = v[h];
#pragma unroll
        for (int off = 16; off; off >>= 1)
#pragma unroll
            for (int h = 0; h < 8; h++)
                bm[h] = fmaxf(bm[h], __shfl_xor_sync(FULL, bm[h], off));

        float sc[8];
#pragma unroll
        for (int h = 0; h < 8; h++) {
            float nm = fmaxf(m[h], bm[h]);
            sc[h] = __expf(m[h] - nm);
            s_[h] *= sc[h];
            m[h] = nm;
        }
        float scH = pick8(sc[0], sc[1], sc[2], sc[3], sc[4], sc[5], sc[6], sc[7], h0);
#pragma unroll
        for (int i = 0; i < 8; i++) acc[i] *= scH;

        float w[8];
#pragma unroll
        for (int h = 0; h < 8; h++) {
            w[h] = valid ? __expf(v[h] - m[h]) : 0.f;
            s_[h] += w[h];
        }
        *(float4*)&s_w[wid][lane][0] = make_float4(w[0], w[1], w[2], w[3]);
        *(float4*)&s_w[wid][lane][4] = make_float4(w[4], w[5], w[6], w[7]);
        __syncwarp();

        const int cnt = min(32, end - base);
        int j = 0;
        for (; j + 4 <= cnt; j += 4) {
            int s0 = __shfl_sync(FULL, sr, j);
            int s1 = __shfl_sync(FULL, sr, j + 1);
            int s2 = __shfl_sync(FULL, sr, j + 2);
            int s3 = __shfl_sync(FULL, sr, j + 3);
            uint4 u0 = ((const uint4*)(g_fth + (size_t)s0 * HD))[lane];
            uint4 u1 = ((const uint4*)(g_fth + (size_t)s1 * HD))[lane];
            uint4 u2 = ((const uint4*)(g_fth + (size_t)s2 * HD))[lane];
            uint4 u3 = ((const uint4*)(g_fth + (size_t)s3 * HD))[lane];
            float w0 = s_w[wid][j][h0], w1 = s_w[wid][j + 1][h0];
            float w2 = s_w[wid][j + 2][h0], w3 = s_w[wid][j + 3][h0];
#pragma unroll
            for (int t = 0; t < 4; t++) {
                float2 f0 = __half22float2(((const __half2*)&u0)[t]);
                float2 f1 = __half22float2(((const __half2*)&u1)[t]);
                float2 f2 = __half22float2(((const __half2*)&u2)[t]);
                float2 f3 = __half22float2(((const __half2*)&u3)[t]);
                acc[2 * t]     += w0 * f0.x + w1 * f1.x + w2 * f2.x + w3 * f3.x;
                acc[2 * t + 1] += w0 * f0.y + w1 * f1.y + w2 * f2.y + w3 * f3.y;
            }
        }
        for (; j < cnt; j++) {
            int s0 = __shfl_sync(FULL, sr, j);
            uint4 u0 = ((const uint4*)(g_fth + (size_t)s0 * HD))[lane];
            float w0 = s_w[wid][j][h0];
#pragma unroll
            for (int t = 0; t < 4; t++) {
                float2 f0 = __half22float2(((const __half2*)&u0)[t]);
                acc[2 * t]     += w0 * f0.x;
                acc[2 * t + 1] += w0 * f0.y;
            }
        }
        __syncwarp();
    }

#pragma unroll
    for (int off = 16; off; off >>= 1)
#pragma unroll
        for (int h = 0; h < 8; h++)
            s_[h] += __shfl_xor_sync(FULL, s_[h], off);
    float inv[8];
#pragma unroll
    for (int h = 0; h < 8; h++) inv[h] = (s_[h] > 0.f) ? 1.f / s_[h] : 0.f;

    // attn output (fp32 exact path)
    for (int p = beg + lane; p < end; p += 32) {
        int e = g_eids[p];
        int s = src[e];
        float4 l0 = *(const float4*)(g_el + (size_t)s * 8);
        float4 l1 = *(const float4*)(g_el + (size_t)s * 8 + 4);
        float lv[8] = {l0.x, l0.y, l0.z, l0.w, l1.x, l1.y, l1.z, l1.w};
        float a[8];
#pragma unroll
        for (int h = 0; h < 8; h++) {
            float t = lv[h] + er[h];
            t = t > 0.f ? t : 0.2f * t;
            a[h] = __expf(t - m[h]) * inv[h];
        }
        *(float4*)(out_attn + (size_t)e * 8)     = make_float4(a[0], a[1], a[2], a[3]);
        *(float4*)(out_attn + (size_t)e * 8 + 4) = make_float4(a[4], a[5], a[6], a[7]);
    }

    // h: normalize by lane's head, reduce across heads (lanes stride 4), mean
    float invH = pick8(inv[0], inv[1], inv[2], inv[3], inv[4], inv[5], inv[6], inv[7], h0);
#pragma unroll
    for (int i = 0; i < 8; i++) acc[i] *= invH;
#pragma unroll
    for (int off = 4; off <= 16; off <<= 1)
#pragma unroll
        for (int i = 0; i < 8; i++)
            acc[i] += __shfl_xor_sync(FULL, acc[i], off);

    if (lane < 4) {
        // lane j holds output cols 8j..8j+7
        float4 b0 = ((const float4*)g_bmean)[lane * 2];
        float4 b1 = ((const float4*)g_bmean)[lane * 2 + 1];
        float4* o = (float4*)(out_h + (size_t)node * 32 + lane * 8);
        o[0] = make_float4(acc[0] * 0.125f + b0.x, acc[1] * 0.125f + b0.y,
                           acc[2] * 0.125f + b0.z, acc[3] * 0.125f + b0.w);
        o[1] = make_float4(acc[4] * 0.125f + b1.x, acc[5] * 0.125f + b1.y,
                           acc[6] * 0.125f + b1.z, acc[7] * 0.125f + b1.w);
    }
}

// ---------------- launch --------------------------------------------------------
extern "C" void kernel_launch(void* const* d_in, const int* in_sizes, int n_in,
                              void* d_out, int out_size) {
    const float* feat = (const float*)d_in[0];
    const int*   src  = (const int*)d_in[1];
    const int*   dst  = (const int*)d_in[2];
    const float* W    = (const float*)d_in[3];
    const float* al   = (const float*)d_in[4];
    const float* ar   = (const float*)d_in[5];
    const float* bias = (const float*)d_in[6];

    int n = in_sizes[0] / INF_;
    int e = in_sizes[1];

    float* out      = (float*)d_out;
    float* out_h    = out;
    float* out_attn = out + (size_t)n * 32;

    const int SMEM = (32768 + 128 * 132 + 2 * 128 * 17) * 4;
    cudaFuncSetAttribute(k_gemm, cudaFuncAttributeMaxDynamicSharedMemorySize, SMEM);

    int nb = (n + 1023) / 1024;

    k_init<<<(n + 255) / 256, 256>>>(n);                          // 0
    k_hist<<<(e + 255) / 256, 256>>>(dst, e);                     // 1
    k_scan1<<<nb, 1024>>>(n);                                     // 2
    k_gemm<<<(n + 127) / 128, 512, SMEM>>>(feat, W, al, ar, n);   // 3 <- profiled
    k_scan2<<<1, 32>>>(nb);                                       // 4
    k_scan3<<<nb, 1024>>>(n, e);                                  // 5
    k_scatter<<<(e + 255) / 256, 256>>>(dst, e);                  // 6
    k_bias<<<1, 32>>>(bias);                                      // 7
    k_agg<<<(n + 7) / 8, 256>>>(src, out_h, out_attn, n);         // 8
}